// round 16
// baseline (speedup 1.0000x reference)
#include <cuda_runtime.h>
#include <cuda_bf16.h>
#include <cstddef>
#include <cstdint>

// Problem constants
#define B_   2
#define S_   2048
#define DM_  1024
#define H_   16
#define DK_  64
#define M_   (B_ * S_)             // 4096 rows
#define OUT_ELEMS  ((long long)M_ * DM_)                 // 4,194,304
#define ATTN_ELEMS ((long long)B_ * H_ * S_ * S_)        // 134,217,728

// ---------------- scratch (device globals) ----------------
__device__ float g_y[M_ * DM_];
__device__ float g_attn[(size_t)B_ * H_ * S_ * S_];      // fallback attn
__device__ __nv_bfloat16 g_pbf[(size_t)B_ * H_ * S_ * S_];   // softmax p in bf16
__device__ __nv_bfloat16 g_inh[3 * M_ * DM_],  g_inl[3 * M_ * DM_];    // split inputs
__device__ __nv_bfloat16 g_wh[4 * DM_ * DM_],  g_wl[4 * DM_ * DM_];    // split weights
__device__ __nv_bfloat16 g_qkvh[3 * M_ * DM_], g_qkvl[3 * M_ * DM_];   // Q,K,V hi/lo
__device__ __nv_bfloat16 g_ctxh[M_ * DM_];                             // ctx bf16
__device__ int g_maskmode;   // 0=uint8, 1=int32, 2=float32

// =====================================================================
// Fast exp via exp2 poly (FMA pipe, no MUFU). Rel err ~1e-7.
// =====================================================================
__device__ __forceinline__ float fexp(float x)
{
    float t = x * 1.442695041f;
    if (t < -126.0f) return 0.0f;
    float fi = floorf(t);
    float f  = t - fi;
    float p  = 1.8775767e-3f;
    p = fmaf(p, f, 8.9893397e-3f);
    p = fmaf(p, f, 5.5826318e-2f);
    p = fmaf(p, f, 2.4015361e-1f);
    p = fmaf(p, f, 6.9315308e-1f);
    p = fmaf(p, f, 1.0f);
    return p * __int_as_float(((int)fi + 127) << 23);
}

// =====================================================================
// Mask storage-format detection (proven)
// =====================================================================
__global__ void detect_mask_kernel(const unsigned char* __restrict__ m)
{
    __shared__ int cnt[4];
    if (threadIdx.x < 4) cnt[threadIdx.x] = 0;
    __syncthreads();
    for (int i = threadIdx.x; i < 65536; i += blockDim.x)
        if (m[i]) atomicAdd(&cnt[i & 3], 1);
    __syncthreads();
    if (threadIdx.x == 0) {
        int mode;
        if (cnt[1] > 0)      mode = 0;
        else if (cnt[0] > 0) mode = 1;
        else                 mode = 2;
        g_maskmode = mode;
    }
}

// =====================================================================
// mma.sync / cp.async helpers
// =====================================================================
__device__ __forceinline__ void ldsm_x4(uint32_t* r, uint32_t addr) {
    asm volatile("ldmatrix.sync.aligned.m8n8.x4.shared.b16 {%0,%1,%2,%3}, [%4];"
                 : "=r"(r[0]), "=r"(r[1]), "=r"(r[2]), "=r"(r[3]) : "r"(addr));
}
__device__ __forceinline__ void ldsm_x4t(uint32_t* r, uint32_t addr) {
    asm volatile("ldmatrix.sync.aligned.m8n8.x4.trans.shared.b16 {%0,%1,%2,%3}, [%4];"
                 : "=r"(r[0]), "=r"(r[1]), "=r"(r[2]), "=r"(r[3]) : "r"(addr));
}
__device__ __forceinline__ void mma_bf16(float* c, const uint32_t* a, const uint32_t* b) {
    asm volatile(
        "mma.sync.aligned.m16n8k16.row.col.f32.bf16.bf16.f32 "
        "{%0,%1,%2,%3}, {%4,%5,%6,%7}, {%8,%9}, {%0,%1,%2,%3};"
        : "+f"(c[0]), "+f"(c[1]), "+f"(c[2]), "+f"(c[3])
        : "r"(a[0]), "r"(a[1]), "r"(a[2]), "r"(a[3]), "r"(b[0]), "r"(b[1]));
}
__device__ __forceinline__ void cp_async16(uint32_t saddr, const void* gptr) {
    asm volatile("cp.async.cg.shared.global [%0], [%1], 16;"
                 :: "r"(saddr), "l"(gptr));
}
__device__ __forceinline__ void cp_commit() {
    asm volatile("cp.async.commit_group;");
}
template<int N>
__device__ __forceinline__ void cp_wait() {
    asm volatile("cp.async.wait_group %0;" :: "n"(N));
}
// streaming (evict-first) 8-byte store: keeps mask L2-resident
__device__ __forceinline__ void st_cs_f2(float* p, float2 v) {
    asm volatile("st.global.cs.v2.f32 [%0], {%1, %2};"
                 :: "l"(p), "f"(v.x), "f"(v.y) : "memory");
}

__device__ __forceinline__ void split_bf16(float x, __nv_bfloat16& h, __nv_bfloat16& l) {
    h = __float2bfloat16_rn(x);
    l = __float2bfloat16_rn(x - __bfloat162float(h));
}

// =====================================================================
// fp32 -> (hi, lo) bf16 splitters
// =====================================================================
__device__ __forceinline__ void split8(const float* src, __nv_bfloat16* hi,
                                       __nv_bfloat16* lo, size_t i)
{
    float4 a = *(const float4*)&src[i];
    float4 b = *(const float4*)&src[i + 4];
    union { __nv_bfloat162 b2[4]; uint4 u; } uh, ul;
    __nv_bfloat16 h0, h1, l0, l1;
    split_bf16(a.x, h0, l0); split_bf16(a.y, h1, l1);
    uh.b2[0] = __halves2bfloat162(h0, h1); ul.b2[0] = __halves2bfloat162(l0, l1);
    split_bf16(a.z, h0, l0); split_bf16(a.w, h1, l1);
    uh.b2[1] = __halves2bfloat162(h0, h1); ul.b2[1] = __halves2bfloat162(l0, l1);
    split_bf16(b.x, h0, l0); split_bf16(b.y, h1, l1);
    uh.b2[2] = __halves2bfloat162(h0, h1); ul.b2[2] = __halves2bfloat162(l0, l1);
    split_bf16(b.z, h0, l0); split_bf16(b.w, h1, l1);
    uh.b2[3] = __halves2bfloat162(h0, h1); ul.b2[3] = __halves2bfloat162(l0, l1);
    *(uint4*)&hi[i] = uh.u;
    *(uint4*)&lo[i] = ul.u;
}

__global__ __launch_bounds__(256) void conv_split3(
    const float* __restrict__ s0, const float* __restrict__ s1,
    const float* __restrict__ s2,
    __nv_bfloat16* __restrict__ hi, __nv_bfloat16* __restrict__ lo)
{
    const float* src = (blockIdx.y == 0) ? s0 : (blockIdx.y == 1) ? s1 : s2;
    size_t base = (size_t)blockIdx.y * (M_ * DM_);
    size_t i = (size_t)(blockIdx.x * 256 + threadIdx.x) * 8;
    split8(src, hi + base, lo + base, i);
}

__global__ __launch_bounds__(256) void conv_split4w(
    const float* __restrict__ s0, const float* __restrict__ s1,
    const float* __restrict__ s2, const float* __restrict__ s3,
    __nv_bfloat16* __restrict__ hi, __nv_bfloat16* __restrict__ lo)
{
    const float* src = (blockIdx.y == 0) ? s0 : (blockIdx.y == 1) ? s1
                     : (blockIdx.y == 2) ? s2 : s3;
    size_t base = (size_t)blockIdx.y * (DM_ * DM_);
    size_t i = (size_t)(blockIdx.x * 256 + threadIdx.x) * 8;
    split8(src, hi + base, lo + base, i);
}

// =====================================================================
// Pre-split GEMM, cp.async double-buffered.
// Q,K (z=0,1): 3-term; V (z=2): 1-term; WO (OUT_FP32): 1-term.
// =====================================================================
#define PADK 72
#define SM_AH 0
#define SM_AL (128 * PADK * 2)
#define SM_BH (2 * 128 * PADK * 2)
#define SM_BL (2 * 128 * PADK * 2 + 64 * PADK * 2)
#define MMA_STAGE (2 * 128 * PADK * 2 + 2 * 64 * PADK * 2)   // 55296
#define MMA_SMEM_BYTES (2 * MMA_STAGE)                        // 110592

template<bool OUT_FP32>
__global__ void __launch_bounds__(256, 2) gemm_bf16(
    const __nv_bfloat16* __restrict__ Ah, const __nv_bfloat16* __restrict__ Al,
    const __nv_bfloat16* __restrict__ Bh, const __nv_bfloat16* __restrict__ Bl,
    const float* __restrict__ Res, float* __restrict__ Cf,
    __nv_bfloat16* __restrict__ Ch, __nv_bfloat16* __restrict__ Cl,
    long aStride, long bStride, long cStride)
{
    extern __shared__ __align__(16) char dsm[];
    const uint32_t sbase = (uint32_t)__cvta_generic_to_shared(dsm);

    const int z = blockIdx.z;
    const bool lo3 = (!OUT_FP32) && (z != 2);
    Ah += (size_t)z * aStride; Al += (size_t)z * aStride;
    Bh += (size_t)z * bStride; Bl += (size_t)z * bStride;
    if (OUT_FP32) { if (Cf) Cf += (size_t)z * cStride; }
    else { Ch += (size_t)z * cStride; Cl += (size_t)z * cStride; }

    const int tid  = threadIdx.x;
    const int lane = tid & 31;
    const int warp = tid >> 5;
    const int wm   = warp & 3;
    const int wn   = warp >> 2;
    const int row0 = blockIdx.y * 128;
    const int n0   = blockIdx.x * 64;

    float acc[2][4][4];
#pragma unroll
    for (int i = 0; i < 2; i++)
#pragma unroll
        for (int j = 0; j < 4; j++)
#pragma unroll
            for (int k = 0; k < 4; k++) acc[i][j][k] = 0.f;

    uint32_t aoff[2], boff[2];
#pragma unroll
    for (int mi = 0; mi < 2; ++mi)
        aoff[mi] = (uint32_t)((wm * 32 + mi * 16 + (lane & 15)) * PADK + (lane >> 4) * 8);
#pragma unroll
    for (int njp = 0; njp < 2; ++njp)
        boff[njp] = (uint32_t)((((lane >> 3) & 1) * 8 + (lane & 7)) * PADK
                               + wn * 32 + njp * 16 + (lane >> 4) * 8);

    const int ar = tid >> 3, ac8 = (tid & 7) * 8;

    auto prefetch = [&](int c, int st) {
        const int k0 = c * 64;
        const uint32_t sb = sbase + st * MMA_STAGE;
#pragma unroll
        for (int i = 0; i < 4; ++i) {
            size_t off = (size_t)(row0 + ar + i * 32) * DM_ + k0 + ac8;
            uint32_t eo = (uint32_t)((ar + i * 32) * PADK + ac8) * 2;
            cp_async16(sb + SM_AH + eo, &Ah[off]);
            if (lo3) cp_async16(sb + SM_AL + eo, &Al[off]);
        }
#pragma unroll
        for (int i = 0; i < 2; ++i) {
            size_t off = (size_t)(k0 + ar + i * 32) * DM_ + n0 + ac8;
            uint32_t eo = (uint32_t)((ar + i * 32) * PADK + ac8) * 2;
            cp_async16(sb + SM_BH + eo, &Bh[off]);
            if (lo3) cp_async16(sb + SM_BL + eo, &Bl[off]);
        }
        cp_commit();
    };

    const int NC = DM_ / 64;
    prefetch(0, 0);
    prefetch(1, 1);

    for (int c = 0; c < NC; ++c) {
        if (c + 1 < NC) cp_wait<1>(); else cp_wait<0>();
        __syncthreads();
        const uint32_t stb = sbase + (c & 1) * MMA_STAGE;
#pragma unroll
        for (int ks = 0; ks < 4; ++ks) {
            uint32_t ah[2][4], al[2][4], bh[2][4], bl[2][4];
#pragma unroll
            for (int mi = 0; mi < 2; ++mi) {
                uint32_t eo = (aoff[mi] + ks * 16) * 2;
                ldsm_x4(ah[mi], stb + SM_AH + eo);
                if (lo3) ldsm_x4(al[mi], stb + SM_AL + eo);
            }
#pragma unroll
            for (int njp = 0; njp < 2; ++njp) {
                uint32_t eo = (boff[njp] + ks * 16 * PADK) * 2;
                ldsm_x4t(bh[njp], stb + SM_BH + eo);
                if (lo3) ldsm_x4t(bl[njp], stb + SM_BL + eo);
            }
#pragma unroll
            for (int mi = 0; mi < 2; ++mi) {
#pragma unroll
                for (int nj = 0; nj < 4; ++nj) {
                    const uint32_t* bhp = &bh[nj >> 1][(nj & 1) * 2];
                    const uint32_t* blp = &bl[nj >> 1][(nj & 1) * 2];
                    mma_bf16(acc[mi][nj], ah[mi], bhp);
                    if (lo3) {
                        mma_bf16(acc[mi][nj], ah[mi], blp);
                        mma_bf16(acc[mi][nj], al[mi], bhp);
                    }
                }
            }
        }
        if (c + 2 < NC) {
            __syncthreads();
            prefetch(c + 2, c & 1);
        }
    }

#pragma unroll
    for (int mi = 0; mi < 2; ++mi) {
#pragma unroll
        for (int nj = 0; nj < 4; ++nj) {
            int rg = row0 + wm * 32 + mi * 16 + (lane >> 2);
            int cg = n0 + wn * 32 + nj * 8 + (lane & 3) * 2;
#pragma unroll
            for (int rr = 0; rr < 2; ++rr) {
                int r = rg + rr * 8;
                float v0 = acc[mi][nj][rr * 2 + 0];
                float v1 = acc[mi][nj][rr * 2 + 1];
                if (OUT_FP32) {
                    if (Res) {
                        float2 rv = *(const float2*)&Res[(size_t)r * DM_ + cg];
                        v0 += rv.x; v1 += rv.y;
                    }
                    *(float2*)&Cf[(size_t)r * DM_ + cg] = make_float2(v0, v1);
                } else {
                    __nv_bfloat16 h0, h1, l0, l1;
                    split_bf16(v0, h0, l0); split_bf16(v1, h1, l1);
                    *(__nv_bfloat162*)&Ch[(size_t)r * DM_ + cg] = __halves2bfloat162(h0, h1);
                    *(__nv_bfloat162*)&Cl[(size_t)r * DM_ + cg] = __halves2bfloat162(l0, l1);
                }
            }
        }
    }
}

// =====================================================================
// Scores from pre-split Q/K (R13 form; attn stores use evict-first
// hint so the L2-resident mask isn't displaced by the 512 MB stream)
// =====================================================================
#define SC_QH 0
#define SC_QL (128 * PADK * 2)
#define SC_KH (2 * 128 * PADK * 2)
#define SC_KL (3 * 128 * PADK * 2)
#define SC_SMEM_BYTES (4 * 128 * PADK * 2)   // 73728

__global__ __launch_bounds__(256) void scores_mma(
    const __nv_bfloat16* __restrict__ Qh, const __nv_bfloat16* __restrict__ Ql,
    const __nv_bfloat16* __restrict__ Kh, const __nv_bfloat16* __restrict__ Kl,
    const unsigned char* __restrict__ mask_u8, float* __restrict__ attn)
{
    extern __shared__ __align__(16) char dsm[];
    const uint32_t sbase = (uint32_t)__cvta_generic_to_shared(dsm);

    const int bh = blockIdx.z;
    const int b  = bh >> 4;
    const int h  = bh & 15;
    const int q0 = blockIdx.y * 128;
    const int k0 = blockIdx.x * 128;
    const int tid  = threadIdx.x;
    const int lane = tid & 31;
    const int warp = tid >> 5;
    const int wm   = warp & 3;
    const int wn   = warp >> 2;
    const int mode = g_maskmode;

    const int r = tid >> 3, c8 = (tid & 7) * 8;
#pragma unroll
    for (int i = 0; i < 4; ++i) {
        size_t qoff = (size_t)(b * S_ + q0 + r + i * 32) * DM_ + h * DK_ + c8;
        size_t koff = (size_t)(b * S_ + k0 + r + i * 32) * DM_ + h * DK_ + c8;
        uint32_t eo = (uint32_t)((r + i * 32) * PADK + c8) * 2;
        cp_async16(sbase + SC_QH + eo, &Qh[qoff]);
        cp_async16(sbase + SC_QL + eo, &Ql[qoff]);
        cp_async16(sbase + SC_KH + eo, &Kh[koff]);
        cp_async16(sbase + SC_KL + eo, &Kl[koff]);
    }
    cp_commit();
    cp_wait<0>();
    __syncthreads();

    float acc[2][8][4];
#pragma unroll
    for (int i = 0; i < 2; i++)
#pragma unroll
        for (int j = 0; j < 8; j++)
#pragma unroll
            for (int k = 0; k < 4; k++) acc[i][j][k] = 0.f;

    uint32_t aoff[2];
#pragma unroll
    for (int mi = 0; mi < 2; ++mi)
        aoff[mi] = (uint32_t)((wm * 32 + mi * 16 + (lane & 15)) * PADK + (lane >> 4) * 8);
    const uint32_t bbase = (uint32_t)((wn * 64 + (lane >> 4) * 8 + (lane & 7)) * PADK
                                      + ((lane >> 3) & 1) * 8);

#pragma unroll
    for (int ks = 0; ks < 4; ++ks) {
        uint32_t ah[2][4], al[2][4], bh[4][4], bl[4][4];
#pragma unroll
        for (int mi = 0; mi < 2; ++mi) {
            uint32_t eo = (aoff[mi] + ks * 16) * 2;
            ldsm_x4(ah[mi], sbase + SC_QH + eo);
            ldsm_x4(al[mi], sbase + SC_QL + eo);
        }
#pragma unroll
        for (int j = 0; j < 4; ++j) {
            uint32_t eo = (bbase + j * 16 * PADK + ks * 16) * 2;
            ldsm_x4(bh[j], sbase + SC_KH + eo);
            ldsm_x4(bl[j], sbase + SC_KL + eo);
        }
#pragma unroll
        for (int mi = 0; mi < 2; ++mi) {
#pragma unroll
            for (int nj = 0; nj < 8; ++nj) {
                const uint32_t* bhp = &bh[nj >> 1][(nj & 1) * 2];
                const uint32_t* blp = &bl[nj >> 1][(nj & 1) * 2];
                mma_bf16(acc[mi][nj], ah[mi], bhp);
                mma_bf16(acc[mi][nj], ah[mi], blp);
                mma_bf16(acc[mi][nj], al[mi], bhp);
            }
        }
    }

    const int*   mask_i32 = (const int*)mask_u8;
    const float* mask_f32 = (const float*)mask_u8;
#pragma unroll
    for (int mi = 0; mi < 2; ++mi) {
#pragma unroll
        for (int nj = 0; nj < 8; ++nj) {
            int qg = q0 + wm * 32 + mi * 16 + (lane >> 2);
            int kg = k0 + wn * 64 + nj * 8 + (lane & 3) * 2;
#pragma unroll
            for (int rr = 0; rr < 2; ++rr) {
                int qr = qg + rr * 8;
                float s0 = acc[mi][nj][rr * 2 + 0] * 0.125f;
                float s1 = acc[mi][nj][rr * 2 + 1] * 0.125f;
                size_t midx = ((size_t)b * S_ + qr) * S_ + kg;
                bool m0, m1;
                if (mode == 1) {
                    int2 mv = *(const int2*)&mask_i32[midx];
                    m0 = mv.x != 0; m1 = mv.y != 0;
                } else if (mode == 0) {
                    m0 = mask_u8[midx] != 0; m1 = mask_u8[midx + 1] != 0;
                } else {
                    float2 mv = *(const float2*)&mask_f32[midx];
                    m0 = mv.x != 0.0f; m1 = mv.y != 0.0f;
                }
                float2 v = make_float2(m0 ? -1e9f : s0, m1 ? -1e9f : s1);
                st_cs_f2(&attn[((size_t)bh * S_ + qr) * S_ + kg], v);
            }
        }
    }
}

// =====================================================================
// Row softmax over 2048; ALSO emits p as plain bf16 for the ctx GEMM
// =====================================================================
__global__ __launch_bounds__(256) void softmax_kernel(
    float* __restrict__ attn, __nv_bfloat16* __restrict__ pbf)
{
    const int tid = threadIdx.x;
    const size_t rbase = (size_t)blockIdx.x * S_ + tid * 8;
    float* p = attn + rbase;
    const int warp = tid >> 5, lane = tid & 31;
    __shared__ float red[8];

    float4 va = *(const float4*)p;
    float4 vb = *(const float4*)(p + 4);
    float v[8] = {va.x, va.y, va.z, va.w, vb.x, vb.y, vb.z, vb.w};

    float m = v[0];
#pragma unroll
    for (int j = 1; j < 8; j++) m = fmaxf(m, v[j]);
#pragma unroll
    for (int o = 16; o > 0; o >>= 1) m = fmaxf(m, __shfl_xor_sync(0xffffffffu, m, o));
    if (lane == 0) red[warp] = m;
    __syncthreads();
    if (tid == 0) {
        float t = red[0];
#pragma unroll
        for (int w = 1; w < 8; w++) t = fmaxf(t, red[w]);
        red[0] = t;
    }
    __syncthreads();
    m = red[0];

    float s = 0.f;
#pragma unroll
    for (int j = 0; j < 8; j++) { v[j] = fexp(v[j] - m); s += v[j]; }
#pragma unroll
    for (int o = 16; o > 0; o >>= 1) s += __shfl_xor_sync(0xffffffffu, s, o);
    __syncthreads();
    if (lane == 0) red[warp] = s;
    __syncthreads();
    if (tid == 0) {
        float t = 0.f;
#pragma unroll
        for (int w = 0; w < 8; w++) t += red[w];
        red[0] = t;
    }
    __syncthreads();
    float inv = 1.0f / red[0];

#pragma unroll
    for (int j = 0; j < 8; j++) v[j] *= inv;
    *(float4*)p       = make_float4(v[0], v[1], v[2], v[3]);
    *(float4*)(p + 4) = make_float4(v[4], v[5], v[6], v[7]);

    union { __nv_bfloat162 b2[4]; uint4 u; } ub;
    ub.b2[0] = __halves2bfloat162(__float2bfloat16_rn(v[0]), __float2bfloat16_rn(v[1]));
    ub.b2[1] = __halves2bfloat162(__float2bfloat16_rn(v[2]), __float2bfloat16_rn(v[3]));
    ub.b2[2] = __halves2bfloat162(__float2bfloat16_rn(v[4]), __float2bfloat16_rn(v[5]));
    ub.b2[3] = __halves2bfloat162(__float2bfloat16_rn(v[6]), __float2bfloat16_rn(v[7]));
    *(uint4*)&pbf[rbase] = ub.u;
}

// =====================================================================
// Context GEMM, cp.async double-buffered: per bh, ctx = p(bf16) @ Vh
// ctx emitted as plain bf16 (WO GEMM is 1-term).
// =====================================================================
#define CTX_A 0
#define CTX_B (128 * PADK * 2)                       // 18432
#define CTX_STAGE (128 * PADK * 2 + 64 * PADK * 2)   // 27648
#define CTX_SMEM_BYTES (2 * CTX_STAGE)               // 55296

__global__ void __launch_bounds__(256, 2) ctx_mma(
    const __nv_bfloat16* __restrict__ P,
    const __nv_bfloat16* __restrict__ Vh,
    __nv_bfloat16* __restrict__ Ch)
{
    extern __shared__ __align__(16) char dsm[];
    const uint32_t sbase = (uint32_t)__cvta_generic_to_shared(dsm);

    const int bh = blockIdx.z;
    const int b  = bh >> 4;
    const int h  = bh & 15;
    const int row0 = blockIdx.y * 128;
    const int tid  = threadIdx.x;
    const int lane = tid & 31;
    const int warp = tid >> 5;
    const int wm   = warp & 3;
    const int wn   = warp >> 2;

    P += (size_t)bh * S_ * S_;
    const size_t voff0 = (size_t)b * S_ * DM_ + h * DK_;

    float acc[2][4][4];
#pragma unroll
    for (int i = 0; i < 2; i++)
#pragma unroll
        for (int j = 0; j < 4; j++)
#pragma unroll
            for (int k = 0; k < 4; k++) acc[i][j][k] = 0.f;

    uint32_t aoff[2], boff[2];
#pragma unroll
    for (int mi = 0; mi < 2; ++mi)
        aoff[mi] = (uint32_t)((wm * 32 + mi * 16 + (lane & 15)) * PADK + (lane >> 4) * 8);
#pragma unroll
    for (int njp = 0; njp < 2; ++njp)
        boff[njp] = (uint32_t)((((lane >> 3) & 1) * 8 + (lane & 7)) * PADK
                               + wn * 32 + njp * 16 + (lane >> 4) * 8);

    const int ar = tid >> 3, ac8 = (tid & 7) * 8;

    auto prefetch = [&](int c, int st) {
        const int k0 = c * 64;
        const uint32_t sb = sbase + st * CTX_STAGE;
#pragma unroll
        for (int i = 0; i < 4; ++i) {
            size_t off = (size_t)(row0 + ar + i * 32) * S_ + k0 + ac8;
            uint32_t eo = (uint32_t)((ar + i * 32) * PADK + ac8) * 2;
            cp_async16(sb + CTX_A + eo, &P[off]);
        }
#pragma unroll
        for (int i = 0; i < 2; ++i) {
            size_t off = voff0 + (size_t)(k0 + ar + i * 32) * DM_ + ac8;
            uint32_t eo = (uint32_t)((ar + i * 32) * PADK + ac8) * 2;
            cp_async16(sb + CTX_B + eo, &Vh[off]);
        }
        cp_commit();
    };

    const int NC = S_ / 64;
    prefetch(0, 0);
    prefetch(1, 1);

    for (int c = 0; c < NC; ++c) {
        if (c + 1 < NC) cp_wait<1>(); else cp_wait<0>();
        __syncthreads();
        const uint32_t stb = sbase + (c & 1) * CTX_STAGE;
#pragma unroll
        for (int ks = 0; ks < 4; ++ks) {
            uint32_t ah[2][4], bh[2][4];
#pragma unroll
            for (int mi = 0; mi < 2; ++mi)
                ldsm_x4(ah[mi], stb + CTX_A + (aoff[mi] + ks * 16) * 2);
#pragma unroll
            for (int njp = 0; njp < 2; ++njp)
                ldsm_x4t(bh[njp], stb + CTX_B + (boff[njp] + ks * 16 * PADK) * 2);
#pragma unroll
            for (int mi = 0; mi < 2; ++mi)
#pragma unroll
                for (int nj = 0; nj < 4; ++nj)
                    mma_bf16(acc[mi][nj], ah[mi], &bh[nj >> 1][(nj & 1) * 2]);
        }
        if (c + 2 < NC) {
            __syncthreads();
            prefetch(c + 2, c & 1);
        }
    }

#pragma unroll
    for (int mi = 0; mi < 2; ++mi) {
#pragma unroll
        for (int nj = 0; nj < 4; ++nj) {
            int rg = row0 + wm * 32 + mi * 16 + (lane >> 2);
            int cg = wn * 32 + nj * 8 + (lane & 3) * 2;
#pragma unroll
            for (int rr = 0; rr < 2; ++rr) {
                int r = rg + rr * 8;
                size_t o = (size_t)(b * S_ + r) * DM_ + h * DK_ + cg;
                *(__nv_bfloat162*)&Ch[o] = __halves2bfloat162(
                    __float2bfloat16_rn(acc[mi][nj][rr * 2 + 0]),
                    __float2bfloat16_rn(acc[mi][nj][rr * 2 + 1]));
            }
        }
    }
}

// =====================================================================
// LayerNorm (unchanged)
// =====================================================================
__global__ __launch_bounds__(256) void ln_kernel(
    const float* __restrict__ y, float* __restrict__ out)
{
    const int tid = threadIdx.x;
    const float* p = y + (size_t)blockIdx.x * DM_;
    float* o = out + (size_t)blockIdx.x * DM_;
    const int warp = tid >> 5, lane = tid & 31;
    __shared__ float red[8];

    float v[4];
#pragma unroll
    for (int j = 0; j < 4; j++) v[j] = p[tid + j * 256];

    float s = v[0] + v[1] + v[2] + v[3];
#pragma unroll
    for (int o2 = 16; o2 > 0; o2 >>= 1) s += __shfl_xor_sync(0xffffffffu, s, o2);
    if (lane == 0) red[warp] = s;
    __syncthreads();
    if (tid == 0) {
        float t = 0.f;
#pragma unroll
        for (int w = 0; w < 8; w++) t += red[w];
        red[0] = t;
    }
    __syncthreads();
    float mu = red[0] * (1.0f / DM_);

    float sq = 0.f;
#pragma unroll
    for (int j = 0; j < 4; j++) { float d = v[j] - mu; sq += d * d; }
#pragma unroll
    for (int o2 = 16; o2 > 0; o2 >>= 1) sq += __shfl_xor_sync(0xffffffffu, sq, o2);
    __syncthreads();
    if (lane == 0) red[warp] = sq;
    __syncthreads();
    if (tid == 0) {
        float t = 0.f;
#pragma unroll
        for (int w = 0; w < 8; w++) t += red[w];
        red[0] = t;
    }
    __syncthreads();
    float inv = rsqrtf(red[0] * (1.0f / DM_) + 1e-5f);

#pragma unroll
    for (int j = 0; j < 4; j++) o[tid + j * 256] = (v[j] - mu) * inv;
}

// =====================================================================
// Launch (R13 serial structure — proven best)
// =====================================================================
extern "C" void kernel_launch(void* const* d_in, const int* in_sizes, int n_in,
                              void* d_out, int out_size)
{
    const float* inQ = (const float*)d_in[0];
    const float* inK = (const float*)d_in[1];
    const float* inV = (const float*)d_in[2];
    const unsigned char* mask = (const unsigned char*)d_in[3];
    const float* WQ = (const float*)d_in[4];
    const float* WK = (const float*)d_in[5];
    const float* WV = (const float*)d_in[6];
    const float* WO = (const float*)d_in[7];
    float* out = (float*)d_out;

    float *Yp, *Ap;
    __nv_bfloat16 *inh, *inl, *wh, *wl, *qkvh, *qkvl, *ctxh, *pbf;
    cudaGetSymbolAddress((void**)&Yp, g_y);
    cudaGetSymbolAddress((void**)&Ap, g_attn);
    cudaGetSymbolAddress((void**)&inh, g_inh);
    cudaGetSymbolAddress((void**)&inl, g_inl);
    cudaGetSymbolAddress((void**)&wh, g_wh);
    cudaGetSymbolAddress((void**)&wl, g_wl);
    cudaGetSymbolAddress((void**)&qkvh, g_qkvh);
    cudaGetSymbolAddress((void**)&qkvl, g_qkvl);
    cudaGetSymbolAddress((void**)&ctxh, g_ctxh);
    cudaGetSymbolAddress((void**)&pbf, g_pbf);

    float* attn = ((long long)out_size >= OUT_ELEMS + ATTN_ELEMS) ? (out + OUT_ELEMS) : Ap;

    cudaFuncSetAttribute(gemm_bf16<true>, cudaFuncAttributeMaxDynamicSharedMemorySize,
                         MMA_SMEM_BYTES);
    cudaFuncSetAttribute(gemm_bf16<false>, cudaFuncAttributeMaxDynamicSharedMemorySize,
                         MMA_SMEM_BYTES);
    cudaFuncSetAttribute(ctx_mma, cudaFuncAttributeMaxDynamicSharedMemorySize,
                         CTX_SMEM_BYTES);
    cudaFuncSetAttribute(scores_mma, cudaFuncAttributeMaxDynamicSharedMemorySize,
                         SC_SMEM_BYTES);

    detect_mask_kernel<<<1, 256>>>(mask);

    conv_split3<<<dim3((M_ * DM_) / 2048, 3), 256>>>(inQ, inK, inV, inh, inl);
    conv_split4w<<<dim3((DM_ * DM_) / 2048, 4), 256>>>(WQ, WK, WV, WO, wh, wl);

    gemm_bf16<false><<<dim3(DM_ / 64, M_ / 128, 3), 256, MMA_SMEM_BYTES>>>(
        inh, inl, wh, wl, nullptr, nullptr, qkvh, qkvl,
        (long)M_ * DM_, (long)DM_ * DM_, (long)M_ * DM_);

    __nv_bfloat16 *Qh = qkvh, *Ql = qkvl;
    __nv_bfloat16 *Kh = qkvh + (size_t)M_ * DM_, *Kl = qkvl + (size_t)M_ * DM_;
    __nv_bfloat16 *Vh = qkvh + 2 * (size_t)M_ * DM_;

    scores_mma<<<dim3(S_ / 128, S_ / 128, B_ * H_), 256, SC_SMEM_BYTES>>>(Qh, Ql, Kh, Kl, mask, attn);
    softmax_kernel<<<B_ * H_ * S_, 256>>>(attn, pbf);
    ctx_mma<<<dim3(1, S_ / 128, B_ * H_), 256, CTX_SMEM_BYTES>>>(pbf, Vh, ctxh);

    gemm_bf16<true><<<dim3(DM_ / 64, M_ / 128, 1), 256, MMA_SMEM_BYTES>>>(
        ctxh, nullptr, wh + 3 * (size_t)DM_ * DM_, nullptr,
        inQ, Yp, nullptr, nullptr, 0, 0, 0);
    ln_kernel<<<M_, 256>>>(Yp, out);
}

// round 17
// speedup vs baseline: 1.1053x; 1.1053x over previous
#include <cuda_runtime.h>
#include <cuda_bf16.h>
#include <cstddef>
#include <cstdint>

// Problem constants
#define B_   2
#define S_   2048
#define DM_  1024
#define H_   16
#define DK_  64
#define M_   (B_ * S_)             // 4096 rows
#define OUT_ELEMS  ((long long)M_ * DM_)                 // 4,194,304
#define ATTN_ELEMS ((long long)B_ * H_ * S_ * S_)        // 134,217,728

// ---------------- scratch (device globals) ----------------
__device__ float g_y[M_ * DM_];
__device__ float g_attn[(size_t)B_ * H_ * S_ * S_];      // fallback attn
__device__ __nv_bfloat16 g_pbf[(size_t)B_ * H_ * S_ * S_];   // softmax p in bf16
__device__ __nv_bfloat16 g_inh[3 * M_ * DM_],  g_inl[3 * M_ * DM_];    // split inputs
__device__ __nv_bfloat16 g_wh[4 * DM_ * DM_],  g_wl[4 * DM_ * DM_];    // split weights
__device__ __nv_bfloat16 g_qkvh[3 * M_ * DM_], g_qkvl[3 * M_ * DM_];   // Q,K,V hi/lo
__device__ __nv_bfloat16 g_ctxh[M_ * DM_];                             // ctx bf16
__device__ int g_maskmode;   // 0=uint8, 1=int32, 2=float32

// =====================================================================
// Fast exp via exp2 poly (FMA pipe, no MUFU). Rel err ~1e-7.
// =====================================================================
__device__ __forceinline__ float fexp(float x)
{
    float t = x * 1.442695041f;
    if (t < -126.0f) return 0.0f;
    float fi = floorf(t);
    float f  = t - fi;
    float p  = 1.8775767e-3f;
    p = fmaf(p, f, 8.9893397e-3f);
    p = fmaf(p, f, 5.5826318e-2f);
    p = fmaf(p, f, 2.4015361e-1f);
    p = fmaf(p, f, 6.9315308e-1f);
    p = fmaf(p, f, 1.0f);
    return p * __int_as_float(((int)fi + 127) << 23);
}

// =====================================================================
// Mask storage-format detection (proven)
// =====================================================================
__global__ void detect_mask_kernel(const unsigned char* __restrict__ m)
{
    __shared__ int cnt[4];
    if (threadIdx.x < 4) cnt[threadIdx.x] = 0;
    __syncthreads();
    for (int i = threadIdx.x; i < 65536; i += blockDim.x)
        if (m[i]) atomicAdd(&cnt[i & 3], 1);
    __syncthreads();
    if (threadIdx.x == 0) {
        int mode;
        if (cnt[1] > 0)      mode = 0;
        else if (cnt[0] > 0) mode = 1;
        else                 mode = 2;
        g_maskmode = mode;
    }
}

// =====================================================================
// mma.sync / cp.async helpers
// =====================================================================
__device__ __forceinline__ void ldsm_x4(uint32_t* r, uint32_t addr) {
    asm volatile("ldmatrix.sync.aligned.m8n8.x4.shared.b16 {%0,%1,%2,%3}, [%4];"
                 : "=r"(r[0]), "=r"(r[1]), "=r"(r[2]), "=r"(r[3]) : "r"(addr));
}
__device__ __forceinline__ void ldsm_x4t(uint32_t* r, uint32_t addr) {
    asm volatile("ldmatrix.sync.aligned.m8n8.x4.trans.shared.b16 {%0,%1,%2,%3}, [%4];"
                 : "=r"(r[0]), "=r"(r[1]), "=r"(r[2]), "=r"(r[3]) : "r"(addr));
}
__device__ __forceinline__ void mma_bf16(float* c, const uint32_t* a, const uint32_t* b) {
    asm volatile(
        "mma.sync.aligned.m16n8k16.row.col.f32.bf16.bf16.f32 "
        "{%0,%1,%2,%3}, {%4,%5,%6,%7}, {%8,%9}, {%0,%1,%2,%3};"
        : "+f"(c[0]), "+f"(c[1]), "+f"(c[2]), "+f"(c[3])
        : "r"(a[0]), "r"(a[1]), "r"(a[2]), "r"(a[3]), "r"(b[0]), "r"(b[1]));
}
__device__ __forceinline__ void cp_async16(uint32_t saddr, const void* gptr) {
    asm volatile("cp.async.cg.shared.global [%0], [%1], 16;"
                 :: "r"(saddr), "l"(gptr));
}
__device__ __forceinline__ void cp_commit() {
    asm volatile("cp.async.commit_group;");
}
template<int N>
__device__ __forceinline__ void cp_wait() {
    asm volatile("cp.async.wait_group %0;" :: "n"(N));
}

__device__ __forceinline__ void split_bf16(float x, __nv_bfloat16& h, __nv_bfloat16& l) {
    h = __float2bfloat16_rn(x);
    l = __float2bfloat16_rn(x - __bfloat162float(h));
}

// =====================================================================
// fp32 -> (hi, lo) bf16 splitters
// =====================================================================
__device__ __forceinline__ void split8(const float* src, __nv_bfloat16* hi,
                                       __nv_bfloat16* lo, size_t i)
{
    float4 a = *(const float4*)&src[i];
    float4 b = *(const float4*)&src[i + 4];
    union { __nv_bfloat162 b2[4]; uint4 u; } uh, ul;
    __nv_bfloat16 h0, h1, l0, l1;
    split_bf16(a.x, h0, l0); split_bf16(a.y, h1, l1);
    uh.b2[0] = __halves2bfloat162(h0, h1); ul.b2[0] = __halves2bfloat162(l0, l1);
    split_bf16(a.z, h0, l0); split_bf16(a.w, h1, l1);
    uh.b2[1] = __halves2bfloat162(h0, h1); ul.b2[1] = __halves2bfloat162(l0, l1);
    split_bf16(b.x, h0, l0); split_bf16(b.y, h1, l1);
    uh.b2[2] = __halves2bfloat162(h0, h1); ul.b2[2] = __halves2bfloat162(l0, l1);
    split_bf16(b.z, h0, l0); split_bf16(b.w, h1, l1);
    uh.b2[3] = __halves2bfloat162(h0, h1); ul.b2[3] = __halves2bfloat162(l0, l1);
    *(uint4*)&hi[i] = uh.u;
    *(uint4*)&lo[i] = ul.u;
}

__global__ __launch_bounds__(256) void conv_split3(
    const float* __restrict__ s0, const float* __restrict__ s1,
    const float* __restrict__ s2,
    __nv_bfloat16* __restrict__ hi, __nv_bfloat16* __restrict__ lo)
{
    const float* src = (blockIdx.y == 0) ? s0 : (blockIdx.y == 1) ? s1 : s2;
    size_t base = (size_t)blockIdx.y * (M_ * DM_);
    size_t i = (size_t)(blockIdx.x * 256 + threadIdx.x) * 8;
    split8(src, hi + base, lo + base, i);
}

__global__ __launch_bounds__(256) void conv_split4w(
    const float* __restrict__ s0, const float* __restrict__ s1,
    const float* __restrict__ s2, const float* __restrict__ s3,
    __nv_bfloat16* __restrict__ hi, __nv_bfloat16* __restrict__ lo)
{
    const float* src = (blockIdx.y == 0) ? s0 : (blockIdx.y == 1) ? s1
                     : (blockIdx.y == 2) ? s2 : s3;
    size_t base = (size_t)blockIdx.y * (DM_ * DM_);
    size_t i = (size_t)(blockIdx.x * 256 + threadIdx.x) * 8;
    split8(src, hi + base, lo + base, i);
}

// =====================================================================
// Pre-split GEMM, cp.async double-buffered.
// Q,K (z=0,1): 3-term; V (z=2): 1-term; WO (OUT_FP32): 1-term.
// =====================================================================
#define PADK 72
#define SM_AH 0
#define SM_AL (128 * PADK * 2)
#define SM_BH (2 * 128 * PADK * 2)
#define SM_BL (2 * 128 * PADK * 2 + 64 * PADK * 2)
#define MMA_STAGE (2 * 128 * PADK * 2 + 2 * 64 * PADK * 2)   // 55296
#define MMA_SMEM_BYTES (2 * MMA_STAGE)                        // 110592

template<bool OUT_FP32>
__global__ void __launch_bounds__(256, 2) gemm_bf16(
    const __nv_bfloat16* __restrict__ Ah, const __nv_bfloat16* __restrict__ Al,
    const __nv_bfloat16* __restrict__ Bh, const __nv_bfloat16* __restrict__ Bl,
    const float* __restrict__ Res, float* __restrict__ Cf,
    __nv_bfloat16* __restrict__ Ch, __nv_bfloat16* __restrict__ Cl,
    long aStride, long bStride, long cStride)
{
    extern __shared__ __align__(16) char dsm[];
    const uint32_t sbase = (uint32_t)__cvta_generic_to_shared(dsm);

    const int z = blockIdx.z;
    const bool lo3 = (!OUT_FP32) && (z != 2);
    Ah += (size_t)z * aStride; Al += (size_t)z * aStride;
    Bh += (size_t)z * bStride; Bl += (size_t)z * bStride;
    if (OUT_FP32) { if (Cf) Cf += (size_t)z * cStride; }
    else { Ch += (size_t)z * cStride; Cl += (size_t)z * cStride; }

    const int tid  = threadIdx.x;
    const int lane = tid & 31;
    const int warp = tid >> 5;
    const int wm   = warp & 3;
    const int wn   = warp >> 2;
    const int row0 = blockIdx.y * 128;
    const int n0   = blockIdx.x * 64;

    float acc[2][4][4];
#pragma unroll
    for (int i = 0; i < 2; i++)
#pragma unroll
        for (int j = 0; j < 4; j++)
#pragma unroll
            for (int k = 0; k < 4; k++) acc[i][j][k] = 0.f;

    uint32_t aoff[2], boff[2];
#pragma unroll
    for (int mi = 0; mi < 2; ++mi)
        aoff[mi] = (uint32_t)((wm * 32 + mi * 16 + (lane & 15)) * PADK + (lane >> 4) * 8);
#pragma unroll
    for (int njp = 0; njp < 2; ++njp)
        boff[njp] = (uint32_t)((((lane >> 3) & 1) * 8 + (lane & 7)) * PADK
                               + wn * 32 + njp * 16 + (lane >> 4) * 8);

    const int ar = tid >> 3, ac8 = (tid & 7) * 8;

    auto prefetch = [&](int c, int st) {
        const int k0 = c * 64;
        const uint32_t sb = sbase + st * MMA_STAGE;
#pragma unroll
        for (int i = 0; i < 4; ++i) {
            size_t off = (size_t)(row0 + ar + i * 32) * DM_ + k0 + ac8;
            uint32_t eo = (uint32_t)((ar + i * 32) * PADK + ac8) * 2;
            cp_async16(sb + SM_AH + eo, &Ah[off]);
            if (lo3) cp_async16(sb + SM_AL + eo, &Al[off]);
        }
#pragma unroll
        for (int i = 0; i < 2; ++i) {
            size_t off = (size_t)(k0 + ar + i * 32) * DM_ + n0 + ac8;
            uint32_t eo = (uint32_t)((ar + i * 32) * PADK + ac8) * 2;
            cp_async16(sb + SM_BH + eo, &Bh[off]);
            if (lo3) cp_async16(sb + SM_BL + eo, &Bl[off]);
        }
        cp_commit();
    };

    const int NC = DM_ / 64;
    prefetch(0, 0);
    prefetch(1, 1);

    for (int c = 0; c < NC; ++c) {
        if (c + 1 < NC) cp_wait<1>(); else cp_wait<0>();
        __syncthreads();
        const uint32_t stb = sbase + (c & 1) * MMA_STAGE;
#pragma unroll
        for (int ks = 0; ks < 4; ++ks) {
            uint32_t ah[2][4], al[2][4], bh[2][4], bl[2][4];
#pragma unroll
            for (int mi = 0; mi < 2; ++mi) {
                uint32_t eo = (aoff[mi] + ks * 16) * 2;
                ldsm_x4(ah[mi], stb + SM_AH + eo);
                if (lo3) ldsm_x4(al[mi], stb + SM_AL + eo);
            }
#pragma unroll
            for (int njp = 0; njp < 2; ++njp) {
                uint32_t eo = (boff[njp] + ks * 16 * PADK) * 2;
                ldsm_x4t(bh[njp], stb + SM_BH + eo);
                if (lo3) ldsm_x4t(bl[njp], stb + SM_BL + eo);
            }
#pragma unroll
            for (int mi = 0; mi < 2; ++mi) {
#pragma unroll
                for (int nj = 0; nj < 4; ++nj) {
                    const uint32_t* bhp = &bh[nj >> 1][(nj & 1) * 2];
                    const uint32_t* blp = &bl[nj >> 1][(nj & 1) * 2];
                    mma_bf16(acc[mi][nj], ah[mi], bhp);
                    if (lo3) {
                        mma_bf16(acc[mi][nj], ah[mi], blp);
                        mma_bf16(acc[mi][nj], al[mi], bhp);
                    }
                }
            }
        }
        if (c + 2 < NC) {
            __syncthreads();
            prefetch(c + 2, c & 1);
        }
    }

#pragma unroll
    for (int mi = 0; mi < 2; ++mi) {
#pragma unroll
        for (int nj = 0; nj < 4; ++nj) {
            int rg = row0 + wm * 32 + mi * 16 + (lane >> 2);
            int cg = n0 + wn * 32 + nj * 8 + (lane & 3) * 2;
#pragma unroll
            for (int rr = 0; rr < 2; ++rr) {
                int r = rg + rr * 8;
                float v0 = acc[mi][nj][rr * 2 + 0];
                float v1 = acc[mi][nj][rr * 2 + 1];
                if (OUT_FP32) {
                    if (Res) {
                        float2 rv = *(const float2*)&Res[(size_t)r * DM_ + cg];
                        v0 += rv.x; v1 += rv.y;
                    }
                    *(float2*)&Cf[(size_t)r * DM_ + cg] = make_float2(v0, v1);
                } else {
                    __nv_bfloat16 h0, h1, l0, l1;
                    split_bf16(v0, h0, l0); split_bf16(v1, h1, l1);
                    *(__nv_bfloat162*)&Ch[(size_t)r * DM_ + cg] = __halves2bfloat162(h0, h1);
                    *(__nv_bfloat162*)&Cl[(size_t)r * DM_ + cg] = __halves2bfloat162(l0, l1);
                }
            }
        }
    }
}

// =====================================================================
// Scores from pre-split Q/K (single chunk, d=64 resident) — proven form
// =====================================================================
#define SC_QH 0
#define SC_QL (128 * PADK * 2)
#define SC_KH (2 * 128 * PADK * 2)
#define SC_KL (3 * 128 * PADK * 2)
#define SC_SMEM_BYTES (4 * 128 * PADK * 2)   // 73728

__global__ __launch_bounds__(256) void scores_mma(
    const __nv_bfloat16* __restrict__ Qh, const __nv_bfloat16* __restrict__ Ql,
    const __nv_bfloat16* __restrict__ Kh, const __nv_bfloat16* __restrict__ Kl,
    const unsigned char* __restrict__ mask_u8, float* __restrict__ attn)
{
    extern __shared__ __align__(16) char dsm[];
    const uint32_t sbase = (uint32_t)__cvta_generic_to_shared(dsm);

    const int bh = blockIdx.z;
    const int b  = bh >> 4;
    const int h  = bh & 15;
    const int q0 = blockIdx.y * 128;
    const int k0 = blockIdx.x * 128;
    const int tid  = threadIdx.x;
    const int lane = tid & 31;
    const int warp = tid >> 5;
    const int wm   = warp & 3;
    const int wn   = warp >> 2;
    const int mode = g_maskmode;

    const int r = tid >> 3, c8 = (tid & 7) * 8;
#pragma unroll
    for (int i = 0; i < 4; ++i) {
        size_t qoff = (size_t)(b * S_ + q0 + r + i * 32) * DM_ + h * DK_ + c8;
        size_t koff = (size_t)(b * S_ + k0 + r + i * 32) * DM_ + h * DK_ + c8;
        uint32_t eo = (uint32_t)((r + i * 32) * PADK + c8) * 2;
        cp_async16(sbase + SC_QH + eo, &Qh[qoff]);
        cp_async16(sbase + SC_QL + eo, &Ql[qoff]);
        cp_async16(sbase + SC_KH + eo, &Kh[koff]);
        cp_async16(sbase + SC_KL + eo, &Kl[koff]);
    }
    cp_commit();
    cp_wait<0>();
    __syncthreads();

    float acc[2][8][4];
#pragma unroll
    for (int i = 0; i < 2; i++)
#pragma unroll
        for (int j = 0; j < 8; j++)
#pragma unroll
            for (int k = 0; k < 4; k++) acc[i][j][k] = 0.f;

    uint32_t aoff[2];
#pragma unroll
    for (int mi = 0; mi < 2; ++mi)
        aoff[mi] = (uint32_t)((wm * 32 + mi * 16 + (lane & 15)) * PADK + (lane >> 4) * 8);
    const uint32_t bbase = (uint32_t)((wn * 64 + (lane >> 4) * 8 + (lane & 7)) * PADK
                                      + ((lane >> 3) & 1) * 8);

#pragma unroll
    for (int ks = 0; ks < 4; ++ks) {
        uint32_t ah[2][4], al[2][4], bh[4][4], bl[4][4];
#pragma unroll
        for (int mi = 0; mi < 2; ++mi) {
            uint32_t eo = (aoff[mi] + ks * 16) * 2;
            ldsm_x4(ah[mi], sbase + SC_QH + eo);
            ldsm_x4(al[mi], sbase + SC_QL + eo);
        }
#pragma unroll
        for (int j = 0; j < 4; ++j) {
            uint32_t eo = (bbase + j * 16 * PADK + ks * 16) * 2;
            ldsm_x4(bh[j], sbase + SC_KH + eo);
            ldsm_x4(bl[j], sbase + SC_KL + eo);
        }
#pragma unroll
        for (int mi = 0; mi < 2; ++mi) {
#pragma unroll
            for (int nj = 0; nj < 8; ++nj) {
                const uint32_t* bhp = &bh[nj >> 1][(nj & 1) * 2];
                const uint32_t* blp = &bl[nj >> 1][(nj & 1) * 2];
                mma_bf16(acc[mi][nj], ah[mi], bhp);
                mma_bf16(acc[mi][nj], ah[mi], blp);
                mma_bf16(acc[mi][nj], al[mi], bhp);
            }
        }
    }

    const int*   mask_i32 = (const int*)mask_u8;
    const float* mask_f32 = (const float*)mask_u8;
#pragma unroll
    for (int mi = 0; mi < 2; ++mi) {
#pragma unroll
        for (int nj = 0; nj < 8; ++nj) {
            int qg = q0 + wm * 32 + mi * 16 + (lane >> 2);
            int kg = k0 + wn * 64 + nj * 8 + (lane & 3) * 2;
#pragma unroll
            for (int rr = 0; rr < 2; ++rr) {
                int qr = qg + rr * 8;
                float s0 = acc[mi][nj][rr * 2 + 0] * 0.125f;
                float s1 = acc[mi][nj][rr * 2 + 1] * 0.125f;
                size_t midx = ((size_t)b * S_ + qr) * S_ + kg;
                bool m0, m1;
                if (mode == 1) {
                    int2 mv = *(const int2*)&mask_i32[midx];
                    m0 = mv.x != 0; m1 = mv.y != 0;
                } else if (mode == 0) {
                    m0 = mask_u8[midx] != 0; m1 = mask_u8[midx + 1] != 0;
                } else {
                    float2 mv = *(const float2*)&mask_f32[midx];
                    m0 = mv.x != 0.0f; m1 = mv.y != 0.0f;
                }
                float2 v = make_float2(m0 ? -1e9f : s0, m1 ? -1e9f : s1);
                *(float2*)&attn[((size_t)bh * S_ + qr) * S_ + kg] = v;
            }
        }
    }
}

// =====================================================================
// Row softmax over 2048; ALSO emits p as plain bf16 for the ctx GEMM
// =====================================================================
__global__ __launch_bounds__(256) void softmax_kernel(
    float* __restrict__ attn, __nv_bfloat16* __restrict__ pbf)
{
    const int tid = threadIdx.x;
    const size_t rbase = (size_t)blockIdx.x * S_ + tid * 8;
    float* p = attn + rbase;
    const int warp = tid >> 5, lane = tid & 31;
    __shared__ float red[8];

    float4 va = *(const float4*)p;
    float4 vb = *(const float4*)(p + 4);
    float v[8] = {va.x, va.y, va.z, va.w, vb.x, vb.y, vb.z, vb.w};

    float m = v[0];
#pragma unroll
    for (int j = 1; j < 8; j++) m = fmaxf(m, v[j]);
#pragma unroll
    for (int o = 16; o > 0; o >>= 1) m = fmaxf(m, __shfl_xor_sync(0xffffffffu, m, o));
    if (lane == 0) red[warp] = m;
    __syncthreads();
    if (tid == 0) {
        float t = red[0];
#pragma unroll
        for (int w = 1; w < 8; w++) t = fmaxf(t, red[w]);
        red[0] = t;
    }
    __syncthreads();
    m = red[0];

    float s = 0.f;
#pragma unroll
    for (int j = 0; j < 8; j++) { v[j] = fexp(v[j] - m); s += v[j]; }
#pragma unroll
    for (int o = 16; o > 0; o >>= 1) s += __shfl_xor_sync(0xffffffffu, s, o);
    __syncthreads();
    if (lane == 0) red[warp] = s;
    __syncthreads();
    if (tid == 0) {
        float t = 0.f;
#pragma unroll
        for (int w = 0; w < 8; w++) t += red[w];
        red[0] = t;
    }
    __syncthreads();
    float inv = 1.0f / red[0];

#pragma unroll
    for (int j = 0; j < 8; j++) v[j] *= inv;
    *(float4*)p       = make_float4(v[0], v[1], v[2], v[3]);
    *(float4*)(p + 4) = make_float4(v[4], v[5], v[6], v[7]);

    union { __nv_bfloat162 b2[4]; uint4 u; } ub;
    ub.b2[0] = __halves2bfloat162(__float2bfloat16_rn(v[0]), __float2bfloat16_rn(v[1]));
    ub.b2[1] = __halves2bfloat162(__float2bfloat16_rn(v[2]), __float2bfloat16_rn(v[3]));
    ub.b2[2] = __halves2bfloat162(__float2bfloat16_rn(v[4]), __float2bfloat16_rn(v[5]));
    ub.b2[3] = __halves2bfloat162(__float2bfloat16_rn(v[6]), __float2bfloat16_rn(v[7]));
    *(uint4*)&pbf[rbase] = ub.u;
}

// =====================================================================
// Context GEMM, cp.async double-buffered: per bh, ctx = p(bf16) @ Vh
// ctx emitted as plain bf16 (WO GEMM is 1-term).
// =====================================================================
#define CTX_A 0
#define CTX_B (128 * PADK * 2)                       // 18432
#define CTX_STAGE (128 * PADK * 2 + 64 * PADK * 2)   // 27648
#define CTX_SMEM_BYTES (2 * CTX_STAGE)               // 55296

__global__ void __launch_bounds__(256, 2) ctx_mma(
    const __nv_bfloat16* __restrict__ P,
    const __nv_bfloat16* __restrict__ Vh,
    __nv_bfloat16* __restrict__ Ch)
{
    extern __shared__ __align__(16) char dsm[];
    const uint32_t sbase = (uint32_t)__cvta_generic_to_shared(dsm);

    const int bh = blockIdx.z;
    const int b  = bh >> 4;
    const int h  = bh & 15;
    const int row0 = blockIdx.y * 128;
    const int tid  = threadIdx.x;
    const int lane = tid & 31;
    const int warp = tid >> 5;
    const int wm   = warp & 3;
    const int wn   = warp >> 2;

    P += (size_t)bh * S_ * S_;
    const size_t voff0 = (size_t)b * S_ * DM_ + h * DK_;

    float acc[2][4][4];
#pragma unroll
    for (int i = 0; i < 2; i++)
#pragma unroll
        for (int j = 0; j < 4; j++)
#pragma unroll
            for (int k = 0; k < 4; k++) acc[i][j][k] = 0.f;

    uint32_t aoff[2], boff[2];
#pragma unroll
    for (int mi = 0; mi < 2; ++mi)
        aoff[mi] = (uint32_t)((wm * 32 + mi * 16 + (lane & 15)) * PADK + (lane >> 4) * 8);
#pragma unroll
    for (int njp = 0; njp < 2; ++njp)
        boff[njp] = (uint32_t)((((lane >> 3) & 1) * 8 + (lane & 7)) * PADK
                               + wn * 32 + njp * 16 + (lane >> 4) * 8);

    const int ar = tid >> 3, ac8 = (tid & 7) * 8;

    auto prefetch = [&](int c, int st) {
        const int k0 = c * 64;
        const uint32_t sb = sbase + st * CTX_STAGE;
#pragma unroll
        for (int i = 0; i < 4; ++i) {
            size_t off = (size_t)(row0 + ar + i * 32) * S_ + k0 + ac8;
            uint32_t eo = (uint32_t)((ar + i * 32) * PADK + ac8) * 2;
            cp_async16(sb + CTX_A + eo, &P[off]);
        }
#pragma unroll
        for (int i = 0; i < 2; ++i) {
            size_t off = voff0 + (size_t)(k0 + ar + i * 32) * DM_ + ac8;
            uint32_t eo = (uint32_t)((ar + i * 32) * PADK + ac8) * 2;
            cp_async16(sb + CTX_B + eo, &Vh[off]);
        }
        cp_commit();
    };

    const int NC = S_ / 64;
    prefetch(0, 0);
    prefetch(1, 1);

    for (int c = 0; c < NC; ++c) {
        if (c + 1 < NC) cp_wait<1>(); else cp_wait<0>();
        __syncthreads();
        const uint32_t stb = sbase + (c & 1) * CTX_STAGE;
#pragma unroll
        for (int ks = 0; ks < 4; ++ks) {
            uint32_t ah[2][4], bh[2][4];
#pragma unroll
            for (int mi = 0; mi < 2; ++mi)
                ldsm_x4(ah[mi], stb + CTX_A + (aoff[mi] + ks * 16) * 2);
#pragma unroll
            for (int njp = 0; njp < 2; ++njp)
                ldsm_x4t(bh[njp], stb + CTX_B + (boff[njp] + ks * 16 * PADK) * 2);
#pragma unroll
            for (int mi = 0; mi < 2; ++mi)
#pragma unroll
                for (int nj = 0; nj < 4; ++nj)
                    mma_bf16(acc[mi][nj], ah[mi], &bh[nj >> 1][(nj & 1) * 2]);
        }
        if (c + 2 < NC) {
            __syncthreads();
            prefetch(c + 2, c & 1);
        }
    }

#pragma unroll
    for (int mi = 0; mi < 2; ++mi) {
#pragma unroll
        for (int nj = 0; nj < 4; ++nj) {
            int rg = row0 + wm * 32 + mi * 16 + (lane >> 2);
            int cg = wn * 32 + nj * 8 + (lane & 3) * 2;
#pragma unroll
            for (int rr = 0; rr < 2; ++rr) {
                int r = rg + rr * 8;
                size_t o = (size_t)(b * S_ + r) * DM_ + h * DK_ + cg;
                *(__nv_bfloat162*)&Ch[o] = __halves2bfloat162(
                    __float2bfloat16_rn(acc[mi][nj][rr * 2 + 0]),
                    __float2bfloat16_rn(acc[mi][nj][rr * 2 + 1]));
            }
        }
    }
}

// =====================================================================
// LayerNorm (unchanged)
// =====================================================================
__global__ __launch_bounds__(256) void ln_kernel(
    const float* __restrict__ y, float* __restrict__ out)
{
    const int tid = threadIdx.x;
    const float* p = y + (size_t)blockIdx.x * DM_;
    float* o = out + (size_t)blockIdx.x * DM_;
    const int warp = tid >> 5, lane = tid & 31;
    __shared__ float red[8];

    float v[4];
#pragma unroll
    for (int j = 0; j < 4; j++) v[j] = p[tid + j * 256];

    float s = v[0] + v[1] + v[2] + v[3];
#pragma unroll
    for (int o2 = 16; o2 > 0; o2 >>= 1) s += __shfl_xor_sync(0xffffffffu, s, o2);
    if (lane == 0) red[warp] = s;
    __syncthreads();
    if (tid == 0) {
        float t = 0.f;
#pragma unroll
        for (int w = 0; w < 8; w++) t += red[w];
        red[0] = t;
    }
    __syncthreads();
    float mu = red[0] * (1.0f / DM_);

    float sq = 0.f;
#pragma unroll
    for (int j = 0; j < 4; j++) { float d = v[j] - mu; sq += d * d; }
#pragma unroll
    for (int o2 = 16; o2 > 0; o2 >>= 1) sq += __shfl_xor_sync(0xffffffffu, sq, o2);
    __syncthreads();
    if (lane == 0) red[warp] = sq;
    __syncthreads();
    if (tid == 0) {
        float t = 0.f;
#pragma unroll
        for (int w = 0; w < 8; w++) t += red[w];
        red[0] = t;
    }
    __syncthreads();
    float inv = rsqrtf(red[0] * (1.0f / DM_) + 1e-5f);

#pragma unroll
    for (int j = 0; j < 4; j++) o[tid + j * 256] = (v[j] - mu) * inv;
}

// =====================================================================
// Launch (R13 serial structure — proven best)
// =====================================================================
extern "C" void kernel_launch(void* const* d_in, const int* in_sizes, int n_in,
                              void* d_out, int out_size)
{
    const float* inQ = (const float*)d_in[0];
    const float* inK = (const float*)d_in[1];
    const float* inV = (const float*)d_in[2];
    const unsigned char* mask = (const unsigned char*)d_in[3];
    const float* WQ = (const float*)d_in[4];
    const float* WK = (const float*)d_in[5];
    const float* WV = (const float*)d_in[6];
    const float* WO = (const float*)d_in[7];
    float* out = (float*)d_out;

    float *Yp, *Ap;
    __nv_bfloat16 *inh, *inl, *wh, *wl, *qkvh, *qkvl, *ctxh, *pbf;
    cudaGetSymbolAddress((void**)&Yp, g_y);
    cudaGetSymbolAddress((void**)&Ap, g_attn);
    cudaGetSymbolAddress((void**)&inh, g_inh);
    cudaGetSymbolAddress((void**)&inl, g_inl);
    cudaGetSymbolAddress((void**)&wh, g_wh);
    cudaGetSymbolAddress((void**)&wl, g_wl);
    cudaGetSymbolAddress((void**)&qkvh, g_qkvh);
    cudaGetSymbolAddress((void**)&qkvl, g_qkvl);
    cudaGetSymbolAddress((void**)&ctxh, g_ctxh);
    cudaGetSymbolAddress((void**)&pbf, g_pbf);

    float* attn = ((long long)out_size >= OUT_ELEMS + ATTN_ELEMS) ? (out + OUT_ELEMS) : Ap;

    cudaFuncSetAttribute(gemm_bf16<true>, cudaFuncAttributeMaxDynamicSharedMemorySize,
                         MMA_SMEM_BYTES);
    cudaFuncSetAttribute(gemm_bf16<false>, cudaFuncAttributeMaxDynamicSharedMemorySize,
                         MMA_SMEM_BYTES);
    cudaFuncSetAttribute(ctx_mma, cudaFuncAttributeMaxDynamicSharedMemorySize,
                         CTX_SMEM_BYTES);
    cudaFuncSetAttribute(scores_mma, cudaFuncAttributeMaxDynamicSharedMemorySize,
                         SC_SMEM_BYTES);

    detect_mask_kernel<<<1, 256>>>(mask);

    conv_split3<<<dim3((M_ * DM_) / 2048, 3), 256>>>(inQ, inK, inV, inh, inl);
    conv_split4w<<<dim3((DM_ * DM_) / 2048, 4), 256>>>(WQ, WK, WV, WO, wh, wl);

    gemm_bf16<false><<<dim3(DM_ / 64, M_ / 128, 3), 256, MMA_SMEM_BYTES>>>(
        inh, inl, wh, wl, nullptr, nullptr, qkvh, qkvl,
        (long)M_ * DM_, (long)DM_ * DM_, (long)M_ * DM_);

    __nv_bfloat16 *Qh = qkvh, *Ql = qkvl;
    __nv_bfloat16 *Kh = qkvh + (size_t)M_ * DM_, *Kl = qkvl + (size_t)M_ * DM_;
    __nv_bfloat16 *Vh = qkvh + 2 * (size_t)M_ * DM_;

    scores_mma<<<dim3(S_ / 128, S_ / 128, B_ * H_), 256, SC_SMEM_BYTES>>>(Qh, Ql, Kh, Kl, mask, attn);
    softmax_kernel<<<B_ * H_ * S_, 256>>>(attn, pbf);
    ctx_mma<<<dim3(1, S_ / 128, B_ * H_), 256, CTX_SMEM_BYTES>>>(pbf, Vh, ctxh);

    gemm_bf16<true><<<dim3(DM_ / 64, M_ / 128, 1), 256, MMA_SMEM_BYTES>>>(
        ctxh, nullptr, wh + 3 * (size_t)DM_ * DM_, nullptr,
        inQ, Yp, nullptr, nullptr, 0, 0, 0);
    ln_kernel<<<M_, 256>>>(Yp, out);
}